// round 13
// baseline (speedup 1.0000x reference)
#include <cuda_runtime.h>
#include <stdint.h>

#define Bc 32
#define Sc 128
#define Hc 128
#define BSH (Bc * Sc * Hc)

typedef unsigned long long ull;

__device__ float g_M[BSH];

// ---------------------------------------------------------------------------
__device__ __forceinline__ float gelu_f(float x) {
    return 0.5f * x * (1.0f + erff(x * 0.7071067811865476f));
}
__device__ __forceinline__ ull dup2(float x) {
    ull r; unsigned int u = __float_as_uint(x);
    asm("mov.b64 %0, {%1, %1};" : "=l"(r) : "r"(u)); return r;
}
__device__ __forceinline__ void fma2(ull &d, ull a, ull b) {
    asm("fma.rn.f32x2 %0, %1, %2, %3;" : "=l"(d) : "l"(a), "l"(b), "l"(d));
}
__device__ __forceinline__ float lo32(ull v) {
    return __uint_as_float((unsigned int)v);
}
__device__ __forceinline__ float hi32(ull v) {
    return __uint_as_float((unsigned int)(v >> 32));
}
__device__ __forceinline__ uint32_t s2u(const void* p) {
    uint32_t a;
    asm("{ .reg .u64 t; cvta.to.shared.u64 t, %1; cvt.u32.u64 %0, t; }" : "=r"(a) : "l"(p));
    return a;
}
__device__ __forceinline__ void cpasync16(uint32_t dst, const void* src) {
    asm volatile("cp.async.ca.shared.global [%0], [%1], 16;" :: "r"(dst), "l"(src));
}
#define CP_COMMIT() asm volatile("cp.async.commit_group;" ::: "memory")
#define CP_WAIT0()  asm volatile("cp.async.wait_group 0;" ::: "memory")
#define CP_WAIT1()  asm volatile("cp.async.wait_group 1;" ::: "memory")

// ---------------------------------------------------------------------------
// Mix kernel v6: R10 geometry (class-batched, warp = (j, 16-t slab), 2 CTA/SM)
// with ZERO-MOV inner loop:
//  - acc packs h-pairs -> X operand loads pre-packed from smem
//  - W pre-duplicated to (v,v) ull pairs in smem at staging (per-warp LDG->STS
//    pipeline, double buffered, 2-chunk lookahead) -> no dup2 in the K loop,
//    no block barriers in the K loop (X staged resident once).
// Class s = ceil((j+1)/16): 16 j's x s slabs -> 2s blocks of 8 warps.
//   Y[h,t] = sum_k X[b,k,h] * W1[j,k,t]; out += gelu(Y+b1)*W2 (atomicAdd)
// Output pre-initialized to base + b2[j].
// ---------------------------------------------------------------------------
#define WDS 18                                   // Wdup row stride in ulls
#define MIX_SMEM_BYTES (16384 * 4 + 2 * 8 * 16 * WDS * 8)   // 64KB + 36KB

__global__ __launch_bounds__(256, 2) void mix_kernel(
    const float* __restrict__ X,     // [B,S,H]
    const float* __restrict__ W1,    // [S,S,S] (this scale)
    const float* __restrict__ b1,    // [S,S]
    const float* __restrict__ W2,    // [S,S]
    float* __restrict__ out)         // [B,S,H], pre-initialized
{
    extern __shared__ __align__(16) float sm[];
    float* Xall = sm;                           // [16s][128] (<= 64KB)
    ull*   Wd   = (ull*)(sm + 16384);           // [2][8][16][WDS]

    const int bx = blockIdx.x;
    const int b  = bx & 31;
    const int cb = bx >> 5;          // 0..71, descending s
    int s, cbase;
    if      (cb < 16) { s = 8; cbase = 0;  }
    else if (cb < 30) { s = 7; cbase = 16; }
    else if (cb < 42) { s = 6; cbase = 30; }
    else if (cb < 52) { s = 5; cbase = 42; }
    else if (cb < 60) { s = 4; cbase = 52; }
    else if (cb < 66) { s = 3; cbase = 60; }
    else if (cb < 70) { s = 2; cbase = 66; }
    else              { s = 1; cbase = 70; }
    const int blk8 = cb - cbase;     // [0, 2s)

    const int tid  = threadIdx.x;
    const int w    = tid >> 5;
    const int lane = tid & 31;
    const int hg   = lane >> 1;      // 16 h-groups of 8
    const int tg   = lane & 1;       // 2 t-groups of 8
    const int h0   = hg * 8;

    const int slab_id = blk8 * 8 + w;
    const int jloc    = slab_id / s;
    const int slabl   = slab_id - jloc * s;
    const int j       = ((s - 1) << 4) + jloc;
    const int t0      = slabl << 4;

    const float* Xg = X + (long)b * Sc * Hc;
    const uint32_t xsb = s2u(Xall);

    // LDG lane roles for W staging: lkk = k-row, lth = t-half (8 floats)
    const int lkk = lane >> 1, lth = lane & 1;
    const float* WgL = W1 + (long)j * 16384 + lkk * 128 + t0 + lth * 8;

    ull acc[4][8];                   // [h-pair][t] = 32 ull = 64 regs
#pragma unroll
    for (int r = 0; r < 4; ++r)
#pragma unroll
        for (int c = 0; c < 8; ++c) acc[r][c] = 0ull;

    // per-warp dup'd STS of one chunk's 8 floats (a=t..t+3, bq=t+4..t+7)
    ull* wbase0 = &Wd[((0 * 8 + w) * 16 + lkk) * WDS + lth * 8];
    ull* wbase1 = &Wd[((1 * 8 + w) * 16 + lkk) * WDS + lth * 8];
    auto stsDup = [&](float4 a, float4 bq, int buf) {
        ull* p = buf ? wbase1 : wbase0;
        ulonglong2 v0; v0.x = dup2(a.x);  v0.y = dup2(a.y);
        ulonglong2 v1; v1.x = dup2(a.z);  v1.y = dup2(a.w);
        ulonglong2 v2; v2.x = dup2(bq.x); v2.y = dup2(bq.y);
        ulonglong2 v3; v3.x = dup2(bq.z); v3.y = dup2(bq.w);
        *(ulonglong2*)(p + 0) = v0;
        *(ulonglong2*)(p + 2) = v1;
        *(ulonglong2*)(p + 4) = v2;
        *(ulonglong2*)(p + 6) = v3;
    };

    // ---- prologue: stage X (cp.async) + W chunk0 (LDG->STS) + chunk1 LDG ----
    {
        const int nx = 2 * s;                // float4 lines per thread
        for (int p = 0; p < nx; ++p) {
            int idx = tid + p * 256;
            int row = idx >> 5, c4 = (idx & 31) * 4;
            cpasync16(xsb + (uint32_t)(row * 128 + c4) * 4,
                      Xg + row * 128 + c4);
        }
        CP_COMMIT();
    }
    {
        float4 a0 = *(const float4*)(WgL);
        float4 b0 = *(const float4*)(WgL + 4);
        stsDup(a0, b0, 0);
    }
    float4 curA, curB;               // chunk c+1 data awaiting STS
    if (s > 1) {
        curA = *(const float4*)(WgL + 16 * 128);
        curB = *(const float4*)(WgL + 16 * 128 + 4);
    }
    CP_WAIT0();
    __syncthreads();                 // X + W chunk0 visible to all

    // ---- K loop: per-warp W pipeline, no block barriers ----
    for (int c = 0; c < s; ++c) {
        float4 nxtA, nxtB;
        if (c + 2 < s) {             // LDG chunk c+2 early (covered by 2 chunks)
            nxtA = *(const float4*)(WgL + (c + 2) * 16 * 128);
            nxtB = *(const float4*)(WgL + (c + 2) * 16 * 128 + 4);
        }
        const int buf = c & 1;
        const float* Xc = Xall + (c * 16) * 128;
        const ull* Wc = &Wd[((buf * 8 + w) * 16) * WDS + tg * 8];
#pragma unroll
        for (int kk = 0; kk < 16; ++kk) {
            ulonglong2 xa = *(const ulonglong2*)&Xc[kk * 128 + h0];     // h-pairs
            ulonglong2 xb = *(const ulonglong2*)&Xc[kk * 128 + h0 + 4];
            const ull* Wk = Wc + kk * WDS;
            ulonglong2 w01 = *(const ulonglong2*)(Wk + 0);
            ulonglong2 w23 = *(const ulonglong2*)(Wk + 2);
            ulonglong2 w45 = *(const ulonglong2*)(Wk + 4);
            ulonglong2 w67 = *(const ulonglong2*)(Wk + 6);
            fma2(acc[0][0], xa.x, w01.x); fma2(acc[0][1], xa.x, w01.y);
            fma2(acc[0][2], xa.x, w23.x); fma2(acc[0][3], xa.x, w23.y);
            fma2(acc[0][4], xa.x, w45.x); fma2(acc[0][5], xa.x, w45.y);
            fma2(acc[0][6], xa.x, w67.x); fma2(acc[0][7], xa.x, w67.y);
            fma2(acc[1][0], xa.y, w01.x); fma2(acc[1][1], xa.y, w01.y);
            fma2(acc[1][2], xa.y, w23.x); fma2(acc[1][3], xa.y, w23.y);
            fma2(acc[1][4], xa.y, w45.x); fma2(acc[1][5], xa.y, w45.y);
            fma2(acc[1][6], xa.y, w67.x); fma2(acc[1][7], xa.y, w67.y);
            fma2(acc[2][0], xb.x, w01.x); fma2(acc[2][1], xb.x, w01.y);
            fma2(acc[2][2], xb.x, w23.x); fma2(acc[2][3], xb.x, w23.y);
            fma2(acc[2][4], xb.x, w45.x); fma2(acc[2][5], xb.x, w45.y);
            fma2(acc[2][6], xb.x, w67.x); fma2(acc[2][7], xb.x, w67.y);
            fma2(acc[3][0], xb.y, w01.x); fma2(acc[3][1], xb.y, w01.y);
            fma2(acc[3][2], xb.y, w23.x); fma2(acc[3][3], xb.y, w23.y);
            fma2(acc[3][4], xb.y, w45.x); fma2(acc[3][5], xb.y, w45.y);
            fma2(acc[3][6], xb.y, w67.x); fma2(acc[3][7], xb.y, w67.y);
        }
        if (c + 1 < s) {
            stsDup(curA, curB, buf ^ 1);
            curA = nxtA; curB = nxtB;
        }
        __syncwarp();
    }

    // ---- epilogue: gelu * W2, reduce over t, atomicAdd into out ----
    float part[8];
#pragma unroll
    for (int r = 0; r < 8; ++r) part[r] = 0.0f;
    const int tbase = t0 + tg * 8;
#pragma unroll
    for (int t = 0; t < 8; ++t) {
        int tt = tbase + t;
        float b1v = b1[j * Sc + tt];   // zero for t > j
        float w2v = W2[j * Sc + tt];   // zero for t > j
#pragma unroll
        for (int hp = 0; hp < 4; ++hp) {
            ull v = acc[hp][t];
            part[2 * hp]     += gelu_f(lo32(v) + b1v) * w2v;
            part[2 * hp + 1] += gelu_f(hi32(v) + b1v) * w2v;
        }
    }
#pragma unroll
    for (int r = 0; r < 8; ++r)
        part[r] += __shfl_xor_sync(0xffffffffu, part[r], 1);
    if (tg == 0) {
        float* o = out + ((long)b * Sc + j) * Hc + h0;
#pragma unroll
        for (int r = 0; r < 8; ++r) atomicAdd(o + r, part[r]);
    }
}

// ---------------------------------------------------------------------------
// init: out[b,j,h] = base[b,j,h] + b2[j]
// ---------------------------------------------------------------------------
__global__ void init_kernel(const float4* __restrict__ base,
                            const float* __restrict__ b2,
                            float4* __restrict__ out)
{
    int i = blockIdx.x * blockDim.x + threadIdx.x;
    if (i < BSH / 4) {
        int j = (i >> 5) & 127;
        float bv = b2[j];
        float4 v = base[i];
        v.x += bv; v.y += bv; v.z += bv; v.w += bv;
        out[i] = v;
    }
}

// ---------------------------------------------------------------------------
// Fused MLP v2 (R10 measured win): 512 threads, unrolled k-loops.
// ---------------------------------------------------------------------------
#define MRS 132
#define MLP_SMEM_BYTES ((2 * 32 * MRS + 2 * 128 * 128) * 4)

__global__ __launch_bounds__(512, 1) void mlp_fused(
    const float* __restrict__ in, const float* __restrict__ Wm1,
    const float* __restrict__ bm1, const float* __restrict__ Wm2,
    const float* __restrict__ bm2, float* __restrict__ out)
{
    extern __shared__ __align__(16) float sm[];
    float* A    = sm;                  // [32][MRS]
    float* Mid  = sm + 32 * MRS;       // [32][MRS]
    float* W1s  = sm + 2 * 32 * MRS;   // [128][128]
    float* W2s  = W1s + 128 * 128;     // [128][128]

    const int tid = threadIdx.x;
    const int r   = tid >> 4;
    const int cg  = tid & 15;
    const int c0  = cg * 8;
    const int r0g = blockIdx.x * 32;
    const uint32_t smb = s2u(sm);

    for (int i = tid; i < 32 * 32; i += 512) {
        int row = i >> 5, c4 = (i & 31) * 4;
        cpasync16(smb + (uint32_t)(row * MRS + c4) * 4,
                  in + (r0g + row) * 128 + c4);
    }
    for (int i = tid; i < 128 * 32; i += 512) {
        int row = i >> 5, c4 = (i & 31) * 4;
        cpasync16(smb + (uint32_t)(2 * 32 * MRS + row * 128 + c4) * 4,
                  Wm1 + row * 128 + c4);
    }
    CP_COMMIT();
    for (int i = tid; i < 128 * 32; i += 512) {
        int row = i >> 5, c4 = (i & 31) * 4;
        cpasync16(smb + (uint32_t)(2 * 32 * MRS + 128 * 128 + row * 128 + c4) * 4,
                  Wm2 + row * 128 + c4);
    }
    CP_COMMIT();

    CP_WAIT1();
    __syncthreads();

    ull acc[4];
#pragma unroll
    for (int c = 0; c < 4; ++c) acc[c] = 0ull;
    {
        const float* Ar = A + r * MRS;
#pragma unroll 8
        for (int k = 0; k < 128; ++k) {
            ull ad = dup2(Ar[k]);
            ulonglong2 w0 = *(const ulonglong2*)&W1s[k * 128 + c0];
            ulonglong2 w1 = *(const ulonglong2*)&W1s[k * 128 + c0 + 4];
            fma2(acc[0], ad, w0.x); fma2(acc[1], ad, w0.y);
            fma2(acc[2], ad, w1.x); fma2(acc[3], ad, w1.y);
        }
        float* Mr = Mid + r * MRS + c0;
#pragma unroll
        for (int c = 0; c < 8; ++c) {
            ull v = acc[c >> 1];
            float y = ((c & 1) ? hi32(v) : lo32(v)) + bm1[c0 + c];
            Mr[c] = gelu_f(y);
        }
    }
    CP_WAIT0();
    __syncthreads();

#pragma unroll
    for (int c = 0; c < 4; ++c) acc[c] = 0ull;
    {
        const float* Mr = Mid + r * MRS;
#pragma unroll 8
        for (int k = 0; k < 128; ++k) {
            ull ad = dup2(Mr[k]);
            ulonglong2 w0 = *(const ulonglong2*)&W2s[k * 128 + c0];
            ulonglong2 w1 = *(const ulonglong2*)&W2s[k * 128 + c0 + 4];
            fma2(acc[0], ad, w0.x); fma2(acc[1], ad, w0.y);
            fma2(acc[2], ad, w1.x); fma2(acc[3], ad, w1.y);
        }
        float o[8];
#pragma unroll
        for (int c = 0; c < 8; ++c) {
            ull v = acc[c >> 1];
            o[c] = ((c & 1) ? hi32(v) : lo32(v)) + bm2[c0 + c];
        }
        float* og = out + (r0g + r) * 128 + c0;
        *(float4*)&og[0] = make_float4(o[0], o[1], o[2], o[3]);
        *(float4*)&og[4] = make_float4(o[4], o[5], o[6], o[7]);
    }
}

// ---------------------------------------------------------------------------
__global__ void copy_kernel(const float4* __restrict__ src,
                            float4* __restrict__ dst, int n4)
{
    int i = blockIdx.x * blockDim.x + threadIdx.x;
    if (i < n4) dst[i] = src[i];
}

// ---------------------------------------------------------------------------
extern "C" void kernel_launch(void* const* d_in, const int* in_sizes, int n_in,
                              void* d_out, int out_size)
{
    const float* trend0 = (const float*)d_in[0];
    const float* trend1 = (const float*)d_in[1];
    const float* trend2 = (const float*)d_in[2];
    const float* W1     = (const float*)d_in[3];
    const float* b1     = (const float*)d_in[4];
    const float* W2     = (const float*)d_in[5];
    const float* b2     = (const float*)d_in[6];
    const float* Wm1    = (const float*)d_in[7];
    const float* bm1    = (const float*)d_in[8];
    const float* Wm2    = (const float*)d_in[9];
    const float* bm2    = (const float*)d_in[10];

    float* out = (float*)d_out;
    float* O0 = out;             // mlp(trend0 + res1)
    float* O1 = out + BSH;       // mlp(trend1 + res0)
    float* O2 = out + 2 * BSH;   // trend2

    float* pM;
    cudaGetSymbolAddress((void**)&pM, g_M);

    cudaFuncSetAttribute(mix_kernel, cudaFuncAttributeMaxDynamicSharedMemorySize,
                         MIX_SMEM_BYTES);
    cudaFuncSetAttribute(mlp_fused, cudaFuncAttributeMaxDynamicSharedMemorySize,
                         MLP_SMEM_BYTES);

    dim3 blk(256);
    dim3 mixGrid(72 * Bc);       // 2304 blocks, descending class size
    dim3 initGrid(BSH / 4 / 256);

    // scale i=0: X = trend2, base = trend1 -> O1 = mlp(M0)
    init_kernel<<<initGrid, blk>>>((const float4*)trend1, b2, (float4*)pM);
    mix_kernel<<<mixGrid, blk, MIX_SMEM_BYTES>>>(trend2, W1, b1, W2, pM);
    mlp_fused<<<128, 512, MLP_SMEM_BYTES>>>(pM, Wm1, bm1, Wm2, bm2, O1);

    // scale i=1: X = O1, base = trend0 -> O0 = mlp(M1)
    init_kernel<<<initGrid, blk>>>((const float4*)trend0, b2 + Sc, (float4*)pM);
    mix_kernel<<<mixGrid, blk, MIX_SMEM_BYTES>>>(O1, W1 + Sc * Sc * Sc,
                                                 b1 + Sc * Sc, W2 + Sc * Sc, pM);
    mlp_fused<<<128, 512, MLP_SMEM_BYTES>>>(pM, Wm1, bm1, Wm2, bm2, O0);

    // out2 = trend2
    copy_kernel<<<BSH / 4 / 256, 256>>>((const float4*)trend2, (float4*)O2,
                                        BSH / 4);
}

// round 14
// speedup vs baseline: 1.4556x; 1.4556x over previous
#include <cuda_runtime.h>
#include <stdint.h>

#define Bc 32
#define Sc 128
#define Hc 128
#define BSH (Bc * Sc * Hc)

typedef unsigned long long ull;

__device__ float g_M[BSH];
__device__ float g_Xt[BSH];   // transposed X: [b][h][s]

// ---------------------------------------------------------------------------
__device__ __forceinline__ float gelu_f(float x) {
    return 0.5f * x * (1.0f + erff(x * 0.7071067811865476f));
}
__device__ __forceinline__ ull dup2(float x) {
    ull r; unsigned int u = __float_as_uint(x);
    asm("mov.b64 %0, {%1, %1};" : "=l"(r) : "r"(u)); return r;
}
__device__ __forceinline__ void fma2(ull &d, ull a, ull b) {
    asm("fma.rn.f32x2 %0, %1, %2, %3;" : "=l"(d) : "l"(a), "l"(b), "l"(d));
}
__device__ __forceinline__ float lo32(ull v) {
    return __uint_as_float((unsigned int)v);
}
__device__ __forceinline__ float hi32(ull v) {
    return __uint_as_float((unsigned int)(v >> 32));
}
__device__ __forceinline__ uint32_t s2u(const void* p) {
    uint32_t a;
    asm("{ .reg .u64 t; cvta.to.shared.u64 t, %1; cvt.u32.u64 %0, t; }" : "=r"(a) : "l"(p));
    return a;
}
__device__ __forceinline__ void cpasync16(uint32_t dst, const void* src) {
    asm volatile("cp.async.ca.shared.global [%0], [%1], 16;" :: "r"(dst), "l"(src));
}
#define CP_COMMIT() asm volatile("cp.async.commit_group;" ::: "memory")
#define CP_WAIT0()  asm volatile("cp.async.wait_group 0;" ::: "memory")
#define CP_WAIT1()  asm volatile("cp.async.wait_group 1;" ::: "memory")

__device__ __forceinline__ uint32_t f2tf32(float f) {
    uint32_t r;
    asm("cvt.rna.tf32.f32 %0, %1;" : "=r"(r) : "f"(f));
    return r;
}
__device__ __forceinline__ void mma_tf32(float* d, const uint32_t* a,
                                         const uint32_t* b) {
    asm volatile(
        "mma.sync.aligned.m16n8k8.row.col.f32.tf32.tf32.f32 "
        "{%0,%1,%2,%3}, {%4,%5,%6,%7}, {%8,%9}, {%0,%1,%2,%3};"
        : "+f"(d[0]), "+f"(d[1]), "+f"(d[2]), "+f"(d[3])
        : "r"(a[0]), "r"(a[1]), "r"(a[2]), "r"(a[3]), "r"(b[0]), "r"(b[1]));
}

// ---------------------------------------------------------------------------
// xt: transpose X[b][s][h] -> Xt[b][h][s]  (one block per b)
// ---------------------------------------------------------------------------
__global__ __launch_bounds__(256) void xt_kernel(const float* __restrict__ X,
                                                 float* __restrict__ Xt)
{
    __shared__ float st[128][129];
    const int tid = threadIdx.x;
    const float* Xb = X + (size_t)blockIdx.x * 16384;
    float* Xtb = Xt + (size_t)blockIdx.x * 16384;
    for (int i = tid; i < 4096; i += 256) {
        int row = i >> 5, c4 = (i & 31) * 4;
        float4 v = *(const float4*)&Xb[row * 128 + c4];
        st[row][c4] = v.x; st[row][c4 + 1] = v.y;
        st[row][c4 + 2] = v.z; st[row][c4 + 3] = v.w;
    }
    __syncthreads();
    for (int i = tid; i < 4096; i += 256) {
        int h = i >> 5, s4 = (i & 31) * 4;
        float4 v = make_float4(st[s4][h], st[s4 + 1][h], st[s4 + 2][h], st[s4 + 3][h]);
        *(float4*)&Xtb[h * 128 + s4] = v;
    }
}

// ---------------------------------------------------------------------------
// Mix kernel v7: tf32 mma.sync (m16n8k8), class-batched, 2 CTA/SM.
// Class s = ceil((j+1)/16): 16 j's x s slabs (16 t) -> 2s blocks of 8 warps.
// Warp computes Y[128h x 16t] over K16 chunks via tensor cores; epilogue
// gelu*W2 reduce -> atomicAdd into pre-initialized out (base + b2[j]).
// ---------------------------------------------------------------------------
#define XSD 20   // Xs row stride (floats) — conflict-free A loads
#define WSD 24   // Ws row stride (floats) — conflict-free B loads

__global__ __launch_bounds__(256, 2) void mix_kernel(
    const float* __restrict__ Xt,    // [B,H,S] transposed
    const float* __restrict__ W1,    // [S,S,S] (this scale)
    const float* __restrict__ b1,    // [S,S]
    const float* __restrict__ W2,    // [S,S]
    float* __restrict__ out)         // [B,S,H], pre-initialized
{
    __shared__ __align__(16) float Xs[2][128 * XSD];      // 20 KB
    __shared__ __align__(16) float Ws[2][8 * 16 * WSD];   // 24 KB

    const int bx = blockIdx.x;
    const int b  = bx & 31;
    const int cb = bx >> 5;          // 0..71, descending s
    int s, cbase;
    if      (cb < 16) { s = 8; cbase = 0;  }
    else if (cb < 30) { s = 7; cbase = 16; }
    else if (cb < 42) { s = 6; cbase = 30; }
    else if (cb < 52) { s = 5; cbase = 42; }
    else if (cb < 60) { s = 4; cbase = 52; }
    else if (cb < 66) { s = 3; cbase = 60; }
    else if (cb < 70) { s = 2; cbase = 66; }
    else              { s = 1; cbase = 70; }
    const int blk8 = cb - cbase;     // [0, 2s)

    const int tid  = threadIdx.x;
    const int w    = tid >> 5;
    const int lane = tid & 31;
    const int r    = lane >> 2;      // group id 0..7
    const int q    = lane & 3;       // thread-in-group

    const int slab_id = blk8 * 8 + w;
    const int jloc    = slab_id / s;
    const int slabl   = slab_id - jloc * s;
    const int j       = ((s - 1) << 4) + jloc;
    const int t0      = slabl << 4;

    const float* Xtb = Xt + (long)b * 16384;
    const uint32_t xsb = s2u(Xs), wsb = s2u(Ws);

    float d[8][2][4];                // [m-tile][n-tile][frag]
#pragma unroll
    for (int mt = 0; mt < 8; ++mt)
#pragma unroll
        for (int nt = 0; nt < 2; ++nt)
#pragma unroll
            for (int c = 0; c < 4; ++c) d[mt][nt][c] = 0.0f;

    // ---- chunk staging: X 128x16 (512 lines) + W 8 slabs 16x16 (512 lines)
    auto issue = [&](int c, int buf) {
        const int k0 = c << 4;
#pragma unroll
        for (int p = 0; p < 2; ++p) {   // X
            int i = tid + p * 256;
            int row = i >> 2, q4 = (i & 3) * 4;
            cpasync16(xsb + (uint32_t)((buf * 128 * XSD) + row * XSD + q4) * 4,
                      Xtb + row * 128 + k0 + q4);
        }
#pragma unroll
        for (int p = 0; p < 2; ++p) {   // W
            int i = tid + p * 256;
            int lw = i >> 6, rem = i & 63;
            int kk = rem >> 2, q4 = (rem & 3) * 4;
            int sid = blk8 * 8 + lw;
            int jl = sid / s;
            int jj = ((s - 1) << 4) + jl;
            int tt = (sid - jl * s) << 4;
            cpasync16(wsb + (uint32_t)((buf * 8 * 16 * WSD) +
                                       (lw * 16 + kk) * WSD + q4) * 4,
                      W1 + (long)jj * 16384 + (k0 + kk) * 128 + tt + q4);
        }
    };

    issue(0, 0);
    CP_COMMIT();
    if (s > 1) { issue(1, 1); CP_COMMIT(); }

    for (int c = 0; c < s; ++c) {
        if (c == s - 1) { CP_WAIT0(); } else { CP_WAIT1(); }
        __syncthreads();
        const int buf = c & 1;
        const float* Xc = &Xs[buf][0];
        const float* Wc = &Ws[buf][w * 16 * WSD];
#pragma unroll
        for (int kh = 0; kh < 2; ++kh) {
            uint32_t B[2][2];
#pragma unroll
            for (int nt = 0; nt < 2; ++nt) {
                B[nt][0] = f2tf32(Wc[(kh * 8 + q) * WSD + nt * 8 + r]);
                B[nt][1] = f2tf32(Wc[(kh * 8 + q + 4) * WSD + nt * 8 + r]);
            }
#pragma unroll
            for (int mt = 0; mt < 8; ++mt) {
                uint32_t A[4];
                A[0] = f2tf32(Xc[(mt * 16 + r) * XSD + kh * 8 + q]);
                A[1] = f2tf32(Xc[(mt * 16 + r + 8) * XSD + kh * 8 + q]);
                A[2] = f2tf32(Xc[(mt * 16 + r) * XSD + kh * 8 + q + 4]);
                A[3] = f2tf32(Xc[(mt * 16 + r + 8) * XSD + kh * 8 + q + 4]);
                mma_tf32(d[mt][0], A, B[0]);
                mma_tf32(d[mt][1], A, B[1]);
            }
        }
        __syncthreads();
        if (c + 2 < s) { issue(c + 2, buf); }
        CP_COMMIT();
    }

    // ---- epilogue: gelu*W2, reduce over t (quad shfl), atomicAdd ----
    float b1v[2][2], w2v[2][2];
#pragma unroll
    for (int nt = 0; nt < 2; ++nt)
#pragma unroll
        for (int cc = 0; cc < 2; ++cc) {
            int t = t0 + nt * 8 + 2 * q + cc;
            b1v[nt][cc] = b1[j * Sc + t];   // zero for t > j
            w2v[nt][cc] = W2[j * Sc + t];   // zero for t > j
        }

    float* o = out + ((long)b * Sc + j) * Hc;
#pragma unroll
    for (int mt = 0; mt < 8; ++mt) {
        float p0 = 0.0f, p1 = 0.0f;
#pragma unroll
        for (int nt = 0; nt < 2; ++nt) {
            p0 += gelu_f(d[mt][nt][0] + b1v[nt][0]) * w2v[nt][0]
                + gelu_f(d[mt][nt][1] + b1v[nt][1]) * w2v[nt][1];
            p1 += gelu_f(d[mt][nt][2] + b1v[nt][0]) * w2v[nt][0]
                + gelu_f(d[mt][nt][3] + b1v[nt][1]) * w2v[nt][1];
        }
        p0 += __shfl_xor_sync(0xffffffffu, p0, 1);
        p0 += __shfl_xor_sync(0xffffffffu, p0, 2);
        p1 += __shfl_xor_sync(0xffffffffu, p1, 1);
        p1 += __shfl_xor_sync(0xffffffffu, p1, 2);
        if (q == 0) {
            atomicAdd(o + mt * 16 + r, p0);
            atomicAdd(o + mt * 16 + r + 8, p1);
        }
    }
}

// ---------------------------------------------------------------------------
// init: out[b,j,h] = base[b,j,h] + b2[j]
// ---------------------------------------------------------------------------
__global__ void init_kernel(const float4* __restrict__ base,
                            const float* __restrict__ b2,
                            float4* __restrict__ out)
{
    int i = blockIdx.x * blockDim.x + threadIdx.x;
    if (i < BSH / 4) {
        int j = (i >> 5) & 127;
        float bv = b2[j];
        float4 v = base[i];
        v.x += bv; v.y += bv; v.z += bv; v.w += bv;
        out[i] = v;
    }
}

// ---------------------------------------------------------------------------
// Fused MLP v2 (R10 measured win): 512 threads, unrolled k-loops.
// ---------------------------------------------------------------------------
#define MRS 132
#define MLP_SMEM_BYTES ((2 * 32 * MRS + 2 * 128 * 128) * 4)

__global__ __launch_bounds__(512, 1) void mlp_fused(
    const float* __restrict__ in, const float* __restrict__ Wm1,
    const float* __restrict__ bm1, const float* __restrict__ Wm2,
    const float* __restrict__ bm2, float* __restrict__ out)
{
    extern __shared__ __align__(16) float sm[];
    float* A    = sm;                  // [32][MRS]
    float* Mid  = sm + 32 * MRS;       // [32][MRS]
    float* W1s  = sm + 2 * 32 * MRS;   // [128][128]
    float* W2s  = W1s + 128 * 128;     // [128][128]

    const int tid = threadIdx.x;
    const int r   = tid >> 4;
    const int cg  = tid & 15;
    const int c0  = cg * 8;
    const int r0g = blockIdx.x * 32;
    const uint32_t smb = s2u(sm);

    for (int i = tid; i < 32 * 32; i += 512) {
        int row = i >> 5, c4 = (i & 31) * 4;
        cpasync16(smb + (uint32_t)(row * MRS + c4) * 4,
                  in + (r0g + row) * 128 + c4);
    }
    for (int i = tid; i < 128 * 32; i += 512) {
        int row = i >> 5, c4 = (i & 31) * 4;
        cpasync16(smb + (uint32_t)(2 * 32 * MRS + row * 128 + c4) * 4,
                  Wm1 + row * 128 + c4);
    }
    CP_COMMIT();
    for (int i = tid; i < 128 * 32; i += 512) {
        int row = i >> 5, c4 = (i & 31) * 4;
        cpasync16(smb + (uint32_t)(2 * 32 * MRS + 128 * 128 + row * 128 + c4) * 4,
                  Wm2 + row * 128 + c4);
    }
    CP_COMMIT();

    CP_WAIT1();
    __syncthreads();

    ull acc[4];
#pragma unroll
    for (int c = 0; c < 4; ++c) acc[c] = 0ull;
    {
        const float* Ar = A + r * MRS;
#pragma unroll 8
        for (int k = 0; k < 128; ++k) {
            ull ad = dup2(Ar[k]);
            ulonglong2 w0 = *(const ulonglong2*)&W1s[k * 128 + c0];
            ulonglong2 w1 = *(const ulonglong2*)&W1s[k * 128 + c0 + 4];
            fma2(acc[0], ad, w0.x); fma2(acc[1], ad, w0.y);
            fma2(acc[2], ad, w1.x); fma2(acc[3], ad, w1.y);
        }
        float* Mr = Mid + r * MRS + c0;
#pragma unroll
        for (int c = 0; c < 8; ++c) {
            ull v = acc[c >> 1];
            float y = ((c & 1) ? hi32(v) : lo32(v)) + bm1[c0 + c];
            Mr[c] = gelu_f(y);
        }
    }
    CP_WAIT0();
    __syncthreads();

#pragma unroll
    for (int c = 0; c < 4; ++c) acc[c] = 0ull;
    {
        const float* Mr = Mid + r * MRS;
#pragma unroll 8
        for (int k = 0; k < 128; ++k) {
            ull ad = dup2(Mr[k]);
            ulonglong2 w0 = *(const ulonglong2*)&W2s[k * 128 + c0];
            ulonglong2 w1 = *(const ulonglong2*)&W2s[k * 128 + c0 + 4];
            fma2(acc[0], ad, w0.x); fma2(acc[1], ad, w0.y);
            fma2(acc[2], ad, w1.x); fma2(acc[3], ad, w1.y);
        }
        float o[8];
#pragma unroll
        for (int c = 0; c < 8; ++c) {
            ull v = acc[c >> 1];
            o[c] = ((c & 1) ? hi32(v) : lo32(v)) + bm2[c0 + c];
        }
        float* og = out + (r0g + r) * 128 + c0;
        *(float4*)&og[0] = make_float4(o[0], o[1], o[2], o[3]);
        *(float4*)&og[4] = make_float4(o[4], o[5], o[6], o[7]);
    }
}

// ---------------------------------------------------------------------------
__global__ void copy_kernel(const float4* __restrict__ src,
                            float4* __restrict__ dst, int n4)
{
    int i = blockIdx.x * blockDim.x + threadIdx.x;
    if (i < n4) dst[i] = src[i];
}

// ---------------------------------------------------------------------------
extern "C" void kernel_launch(void* const* d_in, const int* in_sizes, int n_in,
                              void* d_out, int out_size)
{
    const float* trend0 = (const float*)d_in[0];
    const float* trend1 = (const float*)d_in[1];
    const float* trend2 = (const float*)d_in[2];
    const float* W1     = (const float*)d_in[3];
    const float* b1     = (const float*)d_in[4];
    const float* W2     = (const float*)d_in[5];
    const float* b2     = (const float*)d_in[6];
    const float* Wm1    = (const float*)d_in[7];
    const float* bm1    = (const float*)d_in[8];
    const float* Wm2    = (const float*)d_in[9];
    const float* bm2    = (const float*)d_in[10];

    float* out = (float*)d_out;
    float* O0 = out;             // mlp(trend0 + res1)
    float* O1 = out + BSH;       // mlp(trend1 + res0)
    float* O2 = out + 2 * BSH;   // trend2

    float *pM, *pXt;
    cudaGetSymbolAddress((void**)&pM, g_M);
    cudaGetSymbolAddress((void**)&pXt, g_Xt);

    cudaFuncSetAttribute(mlp_fused, cudaFuncAttributeMaxDynamicSharedMemorySize,
                         MLP_SMEM_BYTES);

    dim3 blk(256);
    dim3 mixGrid(72 * Bc);       // 2304 blocks, descending class size
    dim3 initGrid(BSH / 4 / 256);

    // scale i=0: X = trend2, base = trend1 -> O1 = mlp(M0)
    xt_kernel<<<32, blk>>>(trend2, pXt);
    init_kernel<<<initGrid, blk>>>((const float4*)trend1, b2, (float4*)pM);
    mix_kernel<<<mixGrid, blk>>>(pXt, W1, b1, W2, pM);
    mlp_fused<<<128, 512, MLP_SMEM_BYTES>>>(pM, Wm1, bm1, Wm2, bm2, O1);

    // scale i=1: X = O1, base = trend0 -> O0 = mlp(M1)
    xt_kernel<<<32, blk>>>(O1, pXt);
    init_kernel<<<initGrid, blk>>>((const float4*)trend0, b2 + Sc, (float4*)pM);
    mix_kernel<<<mixGrid, blk>>>(pXt, W1 + Sc * Sc * Sc, b1 + Sc * Sc,
                                 W2 + Sc * Sc, pM);
    mlp_fused<<<128, 512, MLP_SMEM_BYTES>>>(pM, Wm1, bm1, Wm2, bm2, O0);

    // out2 = trend2
    copy_kernel<<<BSH / 4 / 256, 256>>>((const float4*)trend2, (float4*)O2,
                                        BSH / 4);
}

// round 15
// speedup vs baseline: 1.8358x; 1.2612x over previous
#include <cuda_runtime.h>
#include <stdint.h>

#define Bc 32
#define Sc 128
#define Hc 128
#define BSH (Bc * Sc * Hc)

typedef unsigned long long ull;

__device__ float g_M[BSH];
__device__ float g_Xt[BSH];   // transposed X: [b][h][s]

// ---------------------------------------------------------------------------
__device__ __forceinline__ float gelu_f(float x) {
    return 0.5f * x * (1.0f + erff(x * 0.7071067811865476f));
}
__device__ __forceinline__ uint32_t s2u(const void* p) {
    uint32_t a;
    asm("{ .reg .u64 t; cvta.to.shared.u64 t, %1; cvt.u32.u64 %0, t; }" : "=r"(a) : "l"(p));
    return a;
}
__device__ __forceinline__ void cpasync16(uint32_t dst, const void* src) {
    asm volatile("cp.async.ca.shared.global [%0], [%1], 16;" :: "r"(dst), "l"(src));
}
#define CP_COMMIT() asm volatile("cp.async.commit_group;" ::: "memory")
#define CP_WAIT0()  asm volatile("cp.async.wait_group 0;" ::: "memory")
#define CP_WAIT1()  asm volatile("cp.async.wait_group 1;" ::: "memory")

__device__ __forceinline__ uint32_t f2tf32(float f) {
    uint32_t r;
    asm("cvt.rna.tf32.f32 %0, %1;" : "=r"(r) : "f"(f));
    return r;
}
__device__ __forceinline__ void mma_tf32(float* d, const uint32_t* a,
                                         const uint32_t* b) {
    asm volatile(
        "mma.sync.aligned.m16n8k8.row.col.f32.tf32.tf32.f32 "
        "{%0,%1,%2,%3}, {%4,%5,%6,%7}, {%8,%9}, {%0,%1,%2,%3};"
        : "+f"(d[0]), "+f"(d[1]), "+f"(d[2]), "+f"(d[3])
        : "r"(a[0]), "r"(a[1]), "r"(a[2]), "r"(a[3]), "r"(b[0]), "r"(b[1]));
}

// ---------------------------------------------------------------------------
// xt: transpose X[b][s][h] -> Xt[b][h][s]  (one block per b)
// ---------------------------------------------------------------------------
__global__ __launch_bounds__(256) void xt_kernel(const float* __restrict__ X,
                                                 float* __restrict__ Xt)
{
    __shared__ float st[128][129];
    const int tid = threadIdx.x;
    const float* Xb = X + (size_t)blockIdx.x * 16384;
    float* Xtb = Xt + (size_t)blockIdx.x * 16384;
    for (int i = tid; i < 4096; i += 256) {
        int row = i >> 5, c4 = (i & 31) * 4;
        float4 v = *(const float4*)&Xb[row * 128 + c4];
        st[row][c4] = v.x; st[row][c4 + 1] = v.y;
        st[row][c4 + 2] = v.z; st[row][c4 + 3] = v.w;
    }
    __syncthreads();
    for (int i = tid; i < 4096; i += 256) {
        int h = i >> 5, s4 = (i & 31) * 4;
        float4 v = make_float4(st[s4][h], st[s4 + 1][h], st[s4 + 2][h], st[s4 + 3][h]);
        *(float4*)&Xtb[h * 128 + s4] = v;
    }
}

// ---------------------------------------------------------------------------
// Mix kernel v7 (R14 measured win): tf32 mma.sync, class-batched, 2 CTA/SM.
// ---------------------------------------------------------------------------
#define XSD 20
#define WSD 24

__global__ __launch_bounds__(256, 2) void mix_kernel(
    const float* __restrict__ Xt,    // [B,H,S] transposed
    const float* __restrict__ W1,    // [S,S,S] (this scale)
    const float* __restrict__ b1,    // [S,S]
    const float* __restrict__ W2,    // [S,S]
    float* __restrict__ out)         // [B,S,H], pre-initialized
{
    __shared__ __align__(16) float Xs[2][128 * XSD];
    __shared__ __align__(16) float Ws[2][8 * 16 * WSD];

    const int bx = blockIdx.x;
    const int b  = bx & 31;
    const int cb = bx >> 5;
    int s, cbase;
    if      (cb < 16) { s = 8; cbase = 0;  }
    else if (cb < 30) { s = 7; cbase = 16; }
    else if (cb < 42) { s = 6; cbase = 30; }
    else if (cb < 52) { s = 5; cbase = 42; }
    else if (cb < 60) { s = 4; cbase = 52; }
    else if (cb < 66) { s = 3; cbase = 60; }
    else if (cb < 70) { s = 2; cbase = 66; }
    else              { s = 1; cbase = 70; }
    const int blk8 = cb - cbase;

    const int tid  = threadIdx.x;
    const int w    = tid >> 5;
    const int lane = tid & 31;
    const int r    = lane >> 2;
    const int q    = lane & 3;

    const int slab_id = blk8 * 8 + w;
    const int jloc    = slab_id / s;
    const int slabl   = slab_id - jloc * s;
    const int j       = ((s - 1) << 4) + jloc;
    const int t0      = slabl << 4;

    const float* Xtb = Xt + (long)b * 16384;
    const uint32_t xsb = s2u(Xs), wsb = s2u(Ws);

    float d[8][2][4];
#pragma unroll
    for (int mt = 0; mt < 8; ++mt)
#pragma unroll
        for (int nt = 0; nt < 2; ++nt)
#pragma unroll
            for (int c = 0; c < 4; ++c) d[mt][nt][c] = 0.0f;

    auto issue = [&](int c, int buf) {
        const int k0 = c << 4;
#pragma unroll
        for (int p = 0; p < 2; ++p) {   // X
            int i = tid + p * 256;
            int row = i >> 2, q4 = (i & 3) * 4;
            cpasync16(xsb + (uint32_t)((buf * 128 * XSD) + row * XSD + q4) * 4,
                      Xtb + row * 128 + k0 + q4);
        }
#pragma unroll
        for (int p = 0; p < 2; ++p) {   // W
            int i = tid + p * 256;
            int lw = i >> 6, rem = i & 63;
            int kk = rem >> 2, q4 = (rem & 3) * 4;
            int sid = blk8 * 8 + lw;
            int jl = sid / s;
            int jj = ((s - 1) << 4) + jl;
            int tt = (sid - jl * s) << 4;
            cpasync16(wsb + (uint32_t)((buf * 8 * 16 * WSD) +
                                       (lw * 16 + kk) * WSD + q4) * 4,
                      W1 + (long)jj * 16384 + (k0 + kk) * 128 + tt + q4);
        }
    };

    issue(0, 0);
    CP_COMMIT();
    if (s > 1) { issue(1, 1); CP_COMMIT(); }

    for (int c = 0; c < s; ++c) {
        if (c == s - 1) { CP_WAIT0(); } else { CP_WAIT1(); }
        __syncthreads();
        const int buf = c & 1;
        const float* Xc = &Xs[buf][0];
        const float* Wc = &Ws[buf][w * 16 * WSD];
#pragma unroll
        for (int kh = 0; kh < 2; ++kh) {
            uint32_t B[2][2];
#pragma unroll
            for (int nt = 0; nt < 2; ++nt) {
                B[nt][0] = f2tf32(Wc[(kh * 8 + q) * WSD + nt * 8 + r]);
                B[nt][1] = f2tf32(Wc[(kh * 8 + q + 4) * WSD + nt * 8 + r]);
            }
#pragma unroll
            for (int mt = 0; mt < 8; ++mt) {
                uint32_t A[4];
                A[0] = f2tf32(Xc[(mt * 16 + r) * XSD + kh * 8 + q]);
                A[1] = f2tf32(Xc[(mt * 16 + r + 8) * XSD + kh * 8 + q]);
                A[2] = f2tf32(Xc[(mt * 16 + r) * XSD + kh * 8 + q + 4]);
                A[3] = f2tf32(Xc[(mt * 16 + r + 8) * XSD + kh * 8 + q + 4]);
                mma_tf32(d[mt][0], A, B[0]);
                mma_tf32(d[mt][1], A, B[1]);
            }
        }
        __syncthreads();
        if (c + 2 < s) { issue(c + 2, buf); }
        CP_COMMIT();
    }

    float b1v[2][2], w2v[2][2];
#pragma unroll
    for (int nt = 0; nt < 2; ++nt)
#pragma unroll
        for (int cc = 0; cc < 2; ++cc) {
            int t = t0 + nt * 8 + 2 * q + cc;
            b1v[nt][cc] = b1[j * Sc + t];
            w2v[nt][cc] = W2[j * Sc + t];
        }

    float* o = out + ((long)b * Sc + j) * Hc;
#pragma unroll
    for (int mt = 0; mt < 8; ++mt) {
        float p0 = 0.0f, p1 = 0.0f;
#pragma unroll
        for (int nt = 0; nt < 2; ++nt) {
            p0 += gelu_f(d[mt][nt][0] + b1v[nt][0]) * w2v[nt][0]
                + gelu_f(d[mt][nt][1] + b1v[nt][1]) * w2v[nt][1];
            p1 += gelu_f(d[mt][nt][2] + b1v[nt][0]) * w2v[nt][0]
                + gelu_f(d[mt][nt][3] + b1v[nt][1]) * w2v[nt][1];
        }
        p0 += __shfl_xor_sync(0xffffffffu, p0, 1);
        p0 += __shfl_xor_sync(0xffffffffu, p0, 2);
        p1 += __shfl_xor_sync(0xffffffffu, p1, 1);
        p1 += __shfl_xor_sync(0xffffffffu, p1, 2);
        if (q == 0) {
            atomicAdd(o + mt * 16 + r, p0);
            atomicAdd(o + mt * 16 + r + 8, p1);
        }
    }
}

// ---------------------------------------------------------------------------
// init: out[b,j,h] = base[b,j,h] + b2[j]
// ---------------------------------------------------------------------------
__global__ void init_kernel(const float4* __restrict__ base,
                            const float* __restrict__ b2,
                            float4* __restrict__ out)
{
    int i = blockIdx.x * blockDim.x + threadIdx.x;
    if (i < BSH / 4) {
        int j = (i >> 5) & 127;
        float bv = b2[j];
        float4 v = base[i];
        v.x += bv; v.y += bv; v.z += bv; v.w += bv;
        out[i] = v;
    }
}

// ---------------------------------------------------------------------------
// Fused MLP v3: tf32 mma.sync, same fragment layout as mix.
// 128 blocks x 256 threads x 32 rows. Warp = (m-tile of 16, n-quarter of 32).
// Layer1 -> gelu -> Mid(smem) -> Layer2 -> out. Wm2 staged behind layer 1.
// ---------------------------------------------------------------------------
#define AS 132
#define MLP_SMEM_BYTES ((32 * AS + 32 * AS + 128 * AS + 128 * AS) * 4)

__global__ __launch_bounds__(256, 1) void mlp_fused(
    const float* __restrict__ in,    // [4096,128]
    const float* __restrict__ Wm1,   // [128,128] (in,out)
    const float* __restrict__ bm1,   // [128]
    const float* __restrict__ Wm2,   // [128,128]
    const float* __restrict__ bm2,   // [128]
    float* __restrict__ out)         // [4096,128]
{
    extern __shared__ __align__(16) float sm[];
    float* As  = sm;                  // [32][AS]
    float* Mid = sm + 32 * AS;        // [32][AS]
    float* W1s = sm + 64 * AS;        // [128][AS]
    float* W2s = W1s + 128 * AS;      // [128][AS]

    const int tid  = threadIdx.x;
    const int w    = tid >> 5;
    const int lane = tid & 31;
    const int r    = lane >> 2;
    const int q    = lane & 3;
    const int mt   = w & 1;           // m-tile (16 rows)
    const int nq   = w >> 1;          // n-quarter (32 cols)
    const int m0   = mt * 16;
    const int n0   = nq * 32;
    const int r0g  = blockIdx.x * 32;
    const uint32_t smb = s2u(sm);

    // stage A + Wm1 (group A); Wm2 (group B)
    for (int i = tid; i < 32 * 32; i += 256) {
        int row = i >> 5, c4 = (i & 31) * 4;
        cpasync16(smb + (uint32_t)(row * AS + c4) * 4,
                  in + (r0g + row) * 128 + c4);
    }
    for (int i = tid; i < 128 * 32; i += 256) {
        int row = i >> 5, c4 = (i & 31) * 4;
        cpasync16(smb + (uint32_t)(64 * AS + row * AS + c4) * 4,
                  Wm1 + row * 128 + c4);
    }
    CP_COMMIT();
    for (int i = tid; i < 128 * 32; i += 256) {
        int row = i >> 5, c4 = (i & 31) * 4;
        cpasync16(smb + (uint32_t)(64 * AS + 128 * AS + row * AS + c4) * 4,
                  Wm2 + row * 128 + c4);
    }
    CP_COMMIT();

    CP_WAIT1();
    __syncthreads();

    // ---- layer 1: Mid = gelu(A @ Wm1 + bm1) ----
    {
        float d[4][4];
#pragma unroll
        for (int nt = 0; nt < 4; ++nt)
#pragma unroll
            for (int c = 0; c < 4; ++c) d[nt][c] = 0.0f;

#pragma unroll
        for (int kh = 0; kh < 16; ++kh) {
            uint32_t A[4];
            A[0] = f2tf32(As[(m0 + r) * AS + kh * 8 + q]);
            A[1] = f2tf32(As[(m0 + r + 8) * AS + kh * 8 + q]);
            A[2] = f2tf32(As[(m0 + r) * AS + kh * 8 + q + 4]);
            A[3] = f2tf32(As[(m0 + r + 8) * AS + kh * 8 + q + 4]);
#pragma unroll
            for (int nt = 0; nt < 4; ++nt) {
                uint32_t B[2];
                B[0] = f2tf32(W1s[(kh * 8 + q) * AS + n0 + nt * 8 + r]);
                B[1] = f2tf32(W1s[(kh * 8 + q + 4) * AS + n0 + nt * 8 + r]);
                mma_tf32(d[nt], A, B);
            }
        }
        // gelu + bias -> Mid
#pragma unroll
        for (int nt = 0; nt < 4; ++nt) {
            int col = n0 + nt * 8 + 2 * q;
            float bb0 = bm1[col], bb1 = bm1[col + 1];
            Mid[(m0 + r) * AS + col]         = gelu_f(d[nt][0] + bb0);
            Mid[(m0 + r) * AS + col + 1]     = gelu_f(d[nt][1] + bb1);
            Mid[(m0 + r + 8) * AS + col]     = gelu_f(d[nt][2] + bb0);
            Mid[(m0 + r + 8) * AS + col + 1] = gelu_f(d[nt][3] + bb1);
        }
    }
    CP_WAIT0();
    __syncthreads();

    // ---- layer 2: out = Mid @ Wm2 + bm2 ----
    {
        float d[4][4];
#pragma unroll
        for (int nt = 0; nt < 4; ++nt)
#pragma unroll
            for (int c = 0; c < 4; ++c) d[nt][c] = 0.0f;

#pragma unroll
        for (int kh = 0; kh < 16; ++kh) {
            uint32_t A[4];
            A[0] = f2tf32(Mid[(m0 + r) * AS + kh * 8 + q]);
            A[1] = f2tf32(Mid[(m0 + r + 8) * AS + kh * 8 + q]);
            A[2] = f2tf32(Mid[(m0 + r) * AS + kh * 8 + q + 4]);
            A[3] = f2tf32(Mid[(m0 + r + 8) * AS + kh * 8 + q + 4]);
#pragma unroll
            for (int nt = 0; nt < 4; ++nt) {
                uint32_t B[2];
                B[0] = f2tf32(W2s[(kh * 8 + q) * AS + n0 + nt * 8 + r]);
                B[1] = f2tf32(W2s[(kh * 8 + q + 4) * AS + n0 + nt * 8 + r]);
                mma_tf32(d[nt], A, B);
            }
        }
#pragma unroll
        for (int nt = 0; nt < 4; ++nt) {
            int col = n0 + nt * 8 + 2 * q;
            float bb0 = bm2[col], bb1 = bm2[col + 1];
            float* o0 = out + (r0g + m0 + r) * 128 + col;
            float* o1 = out + (r0g + m0 + r + 8) * 128 + col;
            o0[0] = d[nt][0] + bb0; o0[1] = d[nt][1] + bb1;
            o1[0] = d[nt][2] + bb0; o1[1] = d[nt][3] + bb1;
        }
    }
}

// ---------------------------------------------------------------------------
__global__ void copy_kernel(const float4* __restrict__ src,
                            float4* __restrict__ dst, int n4)
{
    int i = blockIdx.x * blockDim.x + threadIdx.x;
    if (i < n4) dst[i] = src[i];
}

// ---------------------------------------------------------------------------
extern "C" void kernel_launch(void* const* d_in, const int* in_sizes, int n_in,
                              void* d_out, int out_size)
{
    const float* trend0 = (const float*)d_in[0];
    const float* trend1 = (const float*)d_in[1];
    const float* trend2 = (const float*)d_in[2];
    const float* W1     = (const float*)d_in[3];
    const float* b1     = (const float*)d_in[4];
    const float* W2     = (const float*)d_in[5];
    const float* b2     = (const float*)d_in[6];
    const float* Wm1    = (const float*)d_in[7];
    const float* bm1    = (const float*)d_in[8];
    const float* Wm2    = (const float*)d_in[9];
    const float* bm2    = (const float*)d_in[10];

    float* out = (float*)d_out;
    float* O0 = out;             // mlp(trend0 + res1)
    float* O1 = out + BSH;       // mlp(trend1 + res0)
    float* O2 = out + 2 * BSH;   // trend2

    float *pM, *pXt;
    cudaGetSymbolAddress((void**)&pM, g_M);
    cudaGetSymbolAddress((void**)&pXt, g_Xt);

    cudaFuncSetAttribute(mlp_fused, cudaFuncAttributeMaxDynamicSharedMemorySize,
                         MLP_SMEM_BYTES);

    dim3 blk(256);
    dim3 mixGrid(72 * Bc);       // 2304 blocks, descending class size
    dim3 initGrid(BSH / 4 / 256);

    // scale i=0: X = trend2, base = trend1 -> O1 = mlp(M0)
    xt_kernel<<<32, blk>>>(trend2, pXt);
    init_kernel<<<initGrid, blk>>>((const float4*)trend1, b2, (float4*)pM);
    mix_kernel<<<mixGrid, blk>>>(pXt, W1, b1, W2, pM);
    mlp_fused<<<128, blk, MLP_SMEM_BYTES>>>(pM, Wm1, bm1, Wm2, bm2, O1);

    // scale i=1: X = O1, base = trend0 -> O0 = mlp(M1)
    xt_kernel<<<32, blk>>>(O1, pXt);
    init_kernel<<<initGrid, blk>>>((const float4*)trend0, b2 + Sc, (float4*)pM);
    mix_kernel<<<mixGrid, blk>>>(pXt, W1 + Sc * Sc * Sc, b1 + Sc * Sc,
                                 W2 + Sc * Sc, pM);
    mlp_fused<<<128, blk, MLP_SMEM_BYTES>>>(pM, Wm1, bm1, Wm2, bm2, O0);

    // out2 = trend2
    copy_kernel<<<BSH / 4 / 256, 256>>>((const float4*)trend2, (float4*)O2,
                                        BSH / 4);
}